// round 3
// baseline (speedup 1.0000x reference)
#include <cuda_runtime.h>
#include <cuda_pipeline.h>
#include <cstdint>

// Problem shape (fixed by reference setup_inputs)
#define BB 16
#define NN 2048
#define DD 64
#define BM 128   // query rows per CTA
#define BN 32    // KV rows per tile
#define NT 128   // threads per CTA (1 thread = 1 query row)

typedef unsigned long long u64;

union F4U { float4 f4; float f[4]; u64 u[2]; };
union F2U { float f[2]; u64 u; };

// Packed f32x2 FMA / MUL (Blackwell sm_100+; ptxas never emits these from C++)
__device__ __forceinline__ u64 fma2(u64 a, u64 b, u64 c) {
    u64 d;
    asm("fma.rn.f32x2 %0, %1, %2, %3;" : "=l"(d) : "l"(a), "l"(b), "l"(c));
    return d;
}
__device__ __forceinline__ u64 mul2(u64 a, u64 b) {
    u64 d;
    asm("mul.rn.f32x2 %0, %1, %2;" : "=l"(d) : "l"(a), "l"(b));
    return d;
}

#define NEG_INF (__int_as_float(0xff800000))

__global__ __launch_bounds__(NT, 2)
void attn_flash_kernel(const float* __restrict__ q, const float* __restrict__ k,
                       const float* __restrict__ v, const float* __restrict__ edge,
                       const int* __restrict__ mask, float* __restrict__ out)
{
    __shared__ float ks[2][BN][DD];   // 2 x 8 KB
    __shared__ float vs[2][BN][DD];   // 2 x 8 KB

    const int b  = blockIdx.y;
    const int q0 = blockIdx.x * BM;
    const int t  = threadIdx.x;
    const int row = q0 + t;

    // ---- Q row into packed registers (only used for b >= 2) ----
    u64 q2[DD / 2];
    if (b >= 2) {
        const float4* qp = reinterpret_cast<const float4*>(q + ((size_t)b * NN + row) * DD);
        #pragma unroll
        for (int i = 0; i < DD / 4; ++i) {
            F4U u; u.f4 = qp[i];
            q2[2 * i]     = u.u[0];
            q2[2 * i + 1] = u.u[1];
        }
    }

    u64 o2[DD / 2];
    #pragma unroll
    for (int i = 0; i < DD / 2; ++i) o2[i] = 0ull;   // bit pattern 0 == {0.f, 0.f}
    float m = NEG_INF, l = 0.f;

    const float4* kbase = reinterpret_cast<const float4*>(k + (size_t)b * NN * DD);
    const float4* vbase = reinterpret_cast<const float4*>(v + (size_t)b * NN * DD);

    constexpr int NTILES = NN / BN;          // 64
    constexpr int LD_PER_THREAD = (BN * DD / 4) / NT;  // 4 float4 per array per thread

    // Prologue: async-load tile 0 into buffer 0
    {
        #pragma unroll
        for (int i = 0; i < LD_PER_THREAD; ++i) {
            int idx = t + i * NT;
            __pipeline_memcpy_async(&reinterpret_cast<float4*>(&ks[0][0][0])[idx],
                                    &kbase[idx], 16);
            __pipeline_memcpy_async(&reinterpret_cast<float4*>(&vs[0][0][0])[idx],
                                    &vbase[idx], 16);
        }
        __pipeline_commit();
    }

    for (int kt = 0; kt < NTILES; ++kt) {
        const int k0  = kt * BN;
        const int buf = kt & 1;

        // Prefetch next tile into the other buffer (overlaps with this tile's compute)
        if (kt + 1 < NTILES) {
            const int nbuf = (kt + 1) & 1;
            const size_t goff = (size_t)(k0 + BN) * DD / 4;
            #pragma unroll
            for (int i = 0; i < LD_PER_THREAD; ++i) {
                int idx = t + i * NT;
                __pipeline_memcpy_async(&reinterpret_cast<float4*>(&ks[nbuf][0][0])[idx],
                                        &kbase[goff + idx], 16);
                __pipeline_memcpy_async(&reinterpret_cast<float4*>(&vs[nbuf][0][0])[idx],
                                        &vbase[goff + idx], 16);
            }
            __pipeline_commit();
            __pipeline_wait_prior(1);   // current tile's loads done; next tile in flight
        } else {
            __pipeline_wait_prior(0);
        }
        __syncthreads();   // all threads' cp.async stores for 'buf' visible

        // ---- scores for this thread's query row ----
        float s[BN];
        if (b < 2) {
            // u[b] = edge_matrix (unscaled, unmasked)
            const float4* ep = reinterpret_cast<const float4*>(edge + (size_t)row * NN + k0);
            #pragma unroll
            for (int j4 = 0; j4 < BN / 4; ++j4) {
                F4U u; u.f4 = ep[j4];
                s[4 * j4]     = u.f[0];
                s[4 * j4 + 1] = u.f[1];
                s[4 * j4 + 2] = u.f[2];
                s[4 * j4 + 3] = u.f[3];
            }
        } else {
            // s[j] = (q . k_j) / 8, packed-f32x2 dot products from broadcast smem
            #pragma unroll
            for (int j = 0; j < BN; ++j) {
                u64 acc0 = 0ull, acc1 = 0ull;
                const float4* kp = reinterpret_cast<const float4*>(&ks[buf][j][0]);
                #pragma unroll
                for (int d4 = 0; d4 < DD / 4; ++d4) {
                    F4U u; u.f4 = kp[d4];
                    acc0 = fma2(q2[2 * d4],     u.u[0], acc0);
                    acc1 = fma2(q2[2 * d4 + 1], u.u[1], acc1);
                }
                F2U a; a.u = acc0;
                F2U c; c.u = acc1;
                s[j] = (a.f[0] + a.f[1] + c.f[0] + c.f[1]) * 0.125f;
            }
            // mask == nonzero -> -inf.
            // ROUND-2 FINDING: harness dtypes are {float32, int32, bfloat16};
            // the jnp bool mask is delivered as int32 (4 B/elem), NOT bytes.
            const int4* mr = reinterpret_cast<const int4*>(
                mask + ((size_t)b * NN + row) * NN + k0);
            #pragma unroll
            for (int w = 0; w < BN / 4; ++w) {
                int4 mw = mr[w];
                if (mw.x) s[4 * w]     = NEG_INF;
                if (mw.y) s[4 * w + 1] = NEG_INF;
                if (mw.z) s[4 * w + 2] = NEG_INF;
                if (mw.w) s[4 * w + 3] = NEG_INF;
            }
        }

        // ---- online softmax update ----
        float tmax = s[0];
        #pragma unroll
        for (int j = 1; j < BN; ++j) tmax = fmaxf(tmax, s[j]);
        float m_new = fmaxf(m, tmax);

        if (m_new > NEG_INF) {   // skip fully-masked tiles (avoids exp(-inf - -inf) NaN)
            float scale = __expf(m - m_new);   // m == -inf -> 0
            float psum = 0.f;
            #pragma unroll
            for (int j = 0; j < BN; ++j) {
                s[j] = __expf(s[j] - m_new);   // -inf -> 0
                psum += s[j];
            }
            l = l * scale + psum;

            F2U sc; sc.f[0] = scale; sc.f[1] = scale;
            #pragma unroll
            for (int i = 0; i < DD / 2; ++i) o2[i] = mul2(o2[i], sc.u);

            // o += p_j * V_j  (broadcast smem reads, packed FMAs)
            #pragma unroll
            for (int j = 0; j < BN; ++j) {
                F2U p; p.f[0] = s[j]; p.f[1] = s[j];
                const float4* vp = reinterpret_cast<const float4*>(&vs[buf][j][0]);
                #pragma unroll
                for (int d4 = 0; d4 < DD / 4; ++d4) {
                    F4U u; u.f4 = vp[d4];
                    o2[2 * d4]     = fma2(p.u, u.u[0], o2[2 * d4]);
                    o2[2 * d4 + 1] = fma2(p.u, u.u[1], o2[2 * d4 + 1]);
                }
            }
            m = m_new;
        }
        __syncthreads();   // protect 'buf' before it is overwritten at kt+2's prefetch
    }

    // ---- epilogue: normalize and store ----
    float inv = 1.0f / l;
    float4* op = reinterpret_cast<float4*>(out + ((size_t)b * NN + row) * DD);
    #pragma unroll
    for (int i = 0; i < DD / 4; ++i) {
        F2U a; a.u = o2[2 * i];
        F2U c; c.u = o2[2 * i + 1];
        float4 r;
        r.x = a.f[0] * inv; r.y = a.f[1] * inv;
        r.z = c.f[0] * inv; r.w = c.f[1] * inv;
        op[i] = r;
    }
}

extern "C" void kernel_launch(void* const* d_in, const int* in_sizes, int n_in,
                              void* d_out, int out_size)
{
    // Identify inputs by element count:
    //   q/k/v: B*N*D = 2,097,152 each — occurrence order is INSERTION order
    //   (q, k, v): Round 2's q<->k swap made rel_err worse (0.73 -> 1.06),
    //   confirming Round 1's assignment was correct.
    //   edge_matrix: N*N = 4,194,304
    //   mask: B*N*N = 67,108,864 (delivered as int32 per harness dtype set)
    const float* q    = nullptr;
    const float* k    = nullptr;
    const float* v    = nullptr;
    const float* edge = nullptr;
    const int*   mask = nullptr;

    const int QKV_ELEMS  = BB * NN * DD;
    const int EDGE_ELEMS = NN * NN;
    int qkv_seen = 0;
    for (int i = 0; i < n_in; ++i) {
        if (in_sizes[i] == EDGE_ELEMS) {
            edge = (const float*)d_in[i];
        } else if (in_sizes[i] == QKV_ELEMS) {
            if      (qkv_seen == 0) q = (const float*)d_in[i];
            else if (qkv_seen == 1) k = (const float*)d_in[i];
            else                    v = (const float*)d_in[i];
            ++qkv_seen;
        } else {
            mask = (const int*)d_in[i];
        }
    }

    dim3 grid(NN / BM, BB);   // (16, 16) = 256 CTAs
    attn_flash_kernel<<<grid, NT>>>(q, k, v, edge, mask, (float*)d_out);
}

// round 7
// speedup vs baseline: 1.3029x; 1.3029x over previous
#include <cuda_runtime.h>
#include <cstdint>

// ---------------- problem shape ----------------
#define BB 16
#define NN 2048
#define DD 64
#define BMQ 128             // q rows per CTA (4 warps x 32 rows)
#define BJ 32               // KV rows per tile
#define NTILES (NN / BJ)    // 64

// smem layout (float offsets). Q/K column-pair-permuted, V plain row-major.
#define QPAD 68
#define KPAD 68
#define VPAD 72
#define SQH 0
#define SQL (128 * QPAD)
#define SKH (256 * QPAD)
#define SKL (SKH + BJ * KPAD)
#define SVH (SKL + BJ * KPAD)
#define SVL (SVH + BJ * VPAD)
#define SM_FLOATS (SVL + BJ * VPAD)
#define SMEM_BYTES (SM_FLOATS * 4)      // 105,472 B -> 2 CTAs/SM

// fp32 -> tf32 (round-to-nearest-even on 10 mantissa bits)
__device__ __forceinline__ uint32_t f2tf(float x) {
    uint32_t u;
    asm("cvt.rna.tf32.f32 %0, %1;" : "=r"(u) : "f"(x));
    return u;
}

// column pair-permutation: within each 8-group, (c, c+4) land at (2*(c&3), 2*(c&3)+1)
__device__ __forceinline__ int permc(int c) {
    return (c & ~7) | ((c & 3) << 1) | ((c >> 2) & 1);
}

// mma.sync m16n8k8 tf32: D = A*B + D (A row-major, B col-major) — sm_80+ baseline PTX
__device__ __forceinline__ void mma8(float* c, const uint32_t* a, uint32_t b0, uint32_t b1) {
    asm volatile(
        "mma.sync.aligned.m16n8k8.row.col.f32.tf32.tf32.f32 "
        "{%0,%1,%2,%3}, {%4,%5,%6,%7}, {%8,%9}, {%0,%1,%2,%3};"
        : "+f"(c[0]), "+f"(c[1]), "+f"(c[2]), "+f"(c[3])
        : "r"(a[0]), "r"(a[1]), "r"(a[2]), "r"(a[3]), "r"(b0), "r"(b1));
}

__global__ __launch_bounds__(128, 2)
void attn_mma_kernel(const float* __restrict__ q, const float* __restrict__ k,
                     const float* __restrict__ v, const float* __restrict__ edge,
                     const int* __restrict__ mask, float* __restrict__ out)
{
    extern __shared__ float sm[];
    const int b  = blockIdx.y;
    const int q0 = blockIdx.x * BMQ;
    const int t  = threadIdx.x;
    const int w  = t >> 5;        // warp 0..3
    const int l  = t & 31;        // lane
    const int g  = l >> 2;        // groupID (fragment row within m8/n8)
    const int qd = l & 3;         // threadID_in_group

    // ---- Q tile: scale 1/8, tf32 hi/lo split, permuted columns (b>=2 only) ----
    if (b >= 2) {
        const float4* q4 = reinterpret_cast<const float4*>(q + ((size_t)b * NN + q0) * DD);
        #pragma unroll
        for (int i = 0; i < 16; ++i) {
            int idx = t + i * 128;
            int r = idx >> 4, c4 = idx & 15;
            float4 x = q4[idx];
            float xs[4] = {x.x * 0.125f, x.y * 0.125f, x.z * 0.125f, x.w * 0.125f};
            #pragma unroll
            for (int e = 0; e < 4; ++e) {
                int pc = permc(4 * c4 + e);
                float h = __uint_as_float(f2tf(xs[e]));
                sm[SQH + r * QPAD + pc] = h;
                sm[SQL + r * QPAD + pc] = __uint_as_float(f2tf(xs[e] - h));
            }
        }
    }

    float sacc[2][4][4];           // S then P fragments: [m-tile][n-tile][c0..c3]
    float oacc[2][8][4];           // O fragments: [m-tile][d-tile][c0..c3]
    float lsum[2][2] = {{0.f, 0.f}, {0.f, 0.f}};   // row sums [m-tile][row-half]
    #pragma unroll
    for (int mt = 0; mt < 2; ++mt)
        #pragma unroll
        for (int n = 0; n < 8; ++n)
            #pragma unroll
            for (int e = 0; e < 4; ++e) oacc[mt][n][e] = 0.f;

    for (int kt = 0; kt < NTILES; ++kt) {
        const int j0 = kt * BJ;

        // ---- stage K (permuted, b>=2) and V (plain) tiles, tf32 hi/lo split ----
        if (b >= 2) {
            const float4* k4 = reinterpret_cast<const float4*>(k + ((size_t)b * NN + j0) * DD);
            #pragma unroll
            for (int i = 0; i < 4; ++i) {
                int idx = t + i * 128;
                int r = idx >> 4, c4 = idx & 15;
                float4 x = k4[idx];
                float xs[4] = {x.x, x.y, x.z, x.w};
                #pragma unroll
                for (int e = 0; e < 4; ++e) {
                    int pc = permc(4 * c4 + e);
                    float h = __uint_as_float(f2tf(xs[e]));
                    sm[SKH + r * KPAD + pc] = h;
                    sm[SKL + r * KPAD + pc] = __uint_as_float(f2tf(xs[e] - h));
                }
            }
        }
        {
            const float4* v4 = reinterpret_cast<const float4*>(v + ((size_t)b * NN + j0) * DD);
            #pragma unroll
            for (int i = 0; i < 4; ++i) {
                int idx = t + i * 128;
                int r = idx >> 4, c4 = idx & 15;
                float4 x = v4[idx];
                float4 h, lo;
                h.x = __uint_as_float(f2tf(x.x)); lo.x = __uint_as_float(f2tf(x.x - h.x));
                h.y = __uint_as_float(f2tf(x.y)); lo.y = __uint_as_float(f2tf(x.y - h.y));
                h.z = __uint_as_float(f2tf(x.z)); lo.z = __uint_as_float(f2tf(x.z - h.z));
                h.w = __uint_as_float(f2tf(x.w)); lo.w = __uint_as_float(f2tf(x.w - h.w));
                *reinterpret_cast<float4*>(&sm[SVH + r * VPAD + 4 * c4]) = h;
                *reinterpret_cast<float4*>(&sm[SVL + r * VPAD + 4 * c4]) = lo;
            }
        }
        __syncthreads();

        // ---- QK^T: S = Qh*Kh + Ql*Kh + Qh*Kl (b>=2) ----
        if (b >= 2) {
            #pragma unroll
            for (int mt = 0; mt < 2; ++mt)
                #pragma unroll
                for (int nt = 0; nt < 4; ++nt)
                    #pragma unroll
                    for (int e = 0; e < 4; ++e) sacc[mt][nt][e] = 0.f;

            #pragma unroll
            for (int kk = 0; kk < 8; ++kk) {
                uint32_t aH[2][4], aL[2][4];
                #pragma unroll
                for (int mt = 0; mt < 2; ++mt) {
                    int r0 = 32 * w + 16 * mt + g;
                    // permuted pairs -> v2 loads: {a0(k=qd), a2(k=qd+4)} / rows r0, r0+8
                    float2 x0 = *reinterpret_cast<const float2*>(&sm[SQH + r0 * QPAD + 8 * kk + 2 * qd]);
                    float2 x1 = *reinterpret_cast<const float2*>(&sm[SQH + (r0 + 8) * QPAD + 8 * kk + 2 * qd]);
                    aH[mt][0] = __float_as_uint(x0.x); aH[mt][1] = __float_as_uint(x1.x);
                    aH[mt][2] = __float_as_uint(x0.y); aH[mt][3] = __float_as_uint(x1.y);
                    float2 y0 = *reinterpret_cast<const float2*>(&sm[SQL + r0 * QPAD + 8 * kk + 2 * qd]);
                    float2 y1 = *reinterpret_cast<const float2*>(&sm[SQL + (r0 + 8) * QPAD + 8 * kk + 2 * qd]);
                    aL[mt][0] = __float_as_uint(y0.x); aL[mt][1] = __float_as_uint(y1.x);
                    aL[mt][2] = __float_as_uint(y0.y); aL[mt][3] = __float_as_uint(y1.y);
                }
                #pragma unroll
                for (int nt = 0; nt < 4; ++nt) {
                    int jn = 8 * nt + g;   // B col n = groupID
                    float2 bh = *reinterpret_cast<const float2*>(&sm[SKH + jn * KPAD + 8 * kk + 2 * qd]);
                    float2 bl = *reinterpret_cast<const float2*>(&sm[SKL + jn * KPAD + 8 * kk + 2 * qd]);
                    uint32_t bh0 = __float_as_uint(bh.x), bh1 = __float_as_uint(bh.y);
                    uint32_t bl0 = __float_as_uint(bl.x), bl1 = __float_as_uint(bl.y);
                    #pragma unroll
                    for (int mt = 0; mt < 2; ++mt) {
                        mma8(sacc[mt][nt], aH[mt], bh0, bh1);
                        mma8(sacc[mt][nt], aL[mt], bh0, bh1);
                        mma8(sacc[mt][nt], aH[mt], bl0, bl1);
                    }
                }
            }
        }

        // ---- softmax numerators: P = exp(S) (masked) or exp(edge); accumulate l ----
        #pragma unroll
        for (int mt = 0; mt < 2; ++mt) {
            int row0 = q0 + 32 * w + 16 * mt + g;
            #pragma unroll
            for (int nt = 0; nt < 4; ++nt) {
                int col = j0 + 8 * nt + 2 * qd;
                float p0, p1, p2, p3;
                if (b < 2) {
                    float2 e0 = *reinterpret_cast<const float2*>(edge + (size_t)row0 * NN + col);
                    float2 e1 = *reinterpret_cast<const float2*>(edge + (size_t)(row0 + 8) * NN + col);
                    p0 = __expf(e0.x); p1 = __expf(e0.y);
                    p2 = __expf(e1.x); p3 = __expf(e1.y);
                } else {
                    int2 m0 = *reinterpret_cast<const int2*>(mask + ((size_t)b * NN + row0) * NN + col);
                    int2 m1 = *reinterpret_cast<const int2*>(mask + ((size_t)b * NN + row0 + 8) * NN + col);
                    p0 = m0.x ? 0.f : __expf(sacc[mt][nt][0]);
                    p1 = m0.y ? 0.f : __expf(sacc[mt][nt][1]);
                    p2 = m1.x ? 0.f : __expf(sacc[mt][nt][2]);
                    p3 = m1.y ? 0.f : __expf(sacc[mt][nt][3]);
                }
                lsum[mt][0] += p0 + p1;
                lsum[mt][1] += p2 + p3;
                sacc[mt][nt][0] = __uint_as_float(f2tf(p0));
                sacc[mt][nt][1] = __uint_as_float(f2tf(p1));
                sacc[mt][nt][2] = __uint_as_float(f2tf(p2));
                sacc[mt][nt][3] = __uint_as_float(f2tf(p3));
            }
        }

        // ---- PV: O += P*Vh + P*Vl. A-frags built from S-frags via quad shuffles ----
        #pragma unroll
        for (int k2 = 0; k2 < 4; ++k2) {
            uint32_t pa[2][4];
            int src0 = (l & ~3) | (qd >> 1);   // lane holding col qd (element parity qd&1)
            int src1 = src0 + 2;               // lane holding col qd+4
            #pragma unroll
            for (int mt = 0; mt < 2; ++mt) {
                float y00 = __shfl_sync(0xffffffffu, sacc[mt][k2][0], src0);
                float y01 = __shfl_sync(0xffffffffu, sacc[mt][k2][1], src0);
                float y10 = __shfl_sync(0xffffffffu, sacc[mt][k2][2], src0);
                float y11 = __shfl_sync(0xffffffffu, sacc[mt][k2][3], src0);
                float z00 = __shfl_sync(0xffffffffu, sacc[mt][k2][0], src1);
                float z01 = __shfl_sync(0xffffffffu, sacc[mt][k2][1], src1);
                float z10 = __shfl_sync(0xffffffffu, sacc[mt][k2][2], src1);
                float z11 = __shfl_sync(0xffffffffu, sacc[mt][k2][3], src1);
                bool od = (qd & 1);
                pa[mt][0] = __float_as_uint(od ? y01 : y00);  // (row g,    k=qd)
                pa[mt][1] = __float_as_uint(od ? y11 : y10);  // (row g+8,  k=qd)
                pa[mt][2] = __float_as_uint(od ? z01 : z00);  // (row g,    k=qd+4)
                pa[mt][3] = __float_as_uint(od ? z11 : z10);  // (row g+8,  k=qd+4)
            }
            #pragma unroll
            for (int nd = 0; nd < 8; ++nd) {
                int jrow = 8 * k2 + qd;
                uint32_t bh0 = __float_as_uint(sm[SVH + jrow * VPAD + 8 * nd + g]);
                uint32_t bh1 = __float_as_uint(sm[SVH + (jrow + 4) * VPAD + 8 * nd + g]);
                uint32_t bl0 = __float_as_uint(sm[SVL + jrow * VPAD + 8 * nd + g]);
                uint32_t bl1 = __float_as_uint(sm[SVL + (jrow + 4) * VPAD + 8 * nd + g]);
                #pragma unroll
                for (int mt = 0; mt < 2; ++mt) {
                    mma8(oacc[mt][nd], pa[mt], bh0, bh1);
                    mma8(oacc[mt][nd], pa[mt], bl0, bl1);
                }
            }
        }
        __syncthreads();   // protect K/V smem before next tile's stores
    }

    // ---- epilogue: reduce row sums across quad, scale, store ----
    float inv[2][2];
    #pragma unroll
    for (int mt = 0; mt < 2; ++mt)
        #pragma unroll
        for (int h = 0; h < 2; ++h) {
            float s = lsum[mt][h];
            s += __shfl_xor_sync(0xffffffffu, s, 1);
            s += __shfl_xor_sync(0xffffffffu, s, 2);
            inv[mt][h] = 1.0f / s;
        }
    #pragma unroll
    for (int mt = 0; mt < 2; ++mt) {
        int row0 = q0 + 32 * w + 16 * mt + g;
        #pragma unroll
        for (int nd = 0; nd < 8; ++nd) {
            int col = 8 * nd + 2 * qd;
            float2 r0v = make_float2(oacc[mt][nd][0] * inv[mt][0], oacc[mt][nd][1] * inv[mt][0]);
            float2 r1v = make_float2(oacc[mt][nd][2] * inv[mt][1], oacc[mt][nd][3] * inv[mt][1]);
            *reinterpret_cast<float2*>(out + ((size_t)b * NN + row0) * DD + col) = r0v;
            *reinterpret_cast<float2*>(out + ((size_t)b * NN + row0 + 8) * DD + col) = r1v;
        }
    }
}

extern "C" void kernel_launch(void* const* d_in, const int* in_sizes, int n_in,
                              void* d_out, int out_size)
{
    // Input identification (verified Rounds 1-3): q/k/v (2,097,152 elems each)
    // in insertion order q,k,v; edge = N*N; mask = B*N*N delivered as int32.
    const float* q = nullptr; const float* k = nullptr; const float* v = nullptr;
    const float* edge = nullptr; const int* mask = nullptr;

    const int QKV_ELEMS = BB * NN * DD;
    const int EDGE_ELEMS = NN * NN;
    int qkv_seen = 0;
    for (int i = 0; i < n_in; ++i) {
        if (in_sizes[i] == EDGE_ELEMS) edge = (const float*)d_in[i];
        else if (in_sizes[i] == QKV_ELEMS) {
            if (qkv_seen == 0) q = (const float*)d_in[i];
            else if (qkv_seen == 1) k = (const float*)d_in[i];
            else v = (const float*)d_in[i];
            ++qkv_seen;
        } else mask = (const int*)d_in[i];
    }

    cudaFuncSetAttribute(attn_mma_kernel, cudaFuncAttributeMaxDynamicSharedMemorySize, SMEM_BYTES);
    dim3 grid(NN / BMQ, BB);   // (16, 16) = 256 CTAs
    attn_mma_kernel<<<grid, 128, SMEM_BYTES>>>(q, k, v, edge, mask, (float*)d_out);
}

// round 9
// speedup vs baseline: 2.0102x; 1.5429x over previous
#include <cuda_runtime.h>
#include <cstdint>

// ---------------- problem shape ----------------
#define BB 16
#define NN 2048
#define DD 64
#define BMQ 128             // q rows per CTA (4 warps x 32 rows)
#define BJ 32               // KV rows per tile
#define NTILES (NN / BJ)    // 64

// smem layout (float offsets). Q/K column-pair-permuted, V plain row-major.
// Pads = 72 -> conflict-free fragment loads (8g+2qd spans 16 banks per phase).
#define QPAD 72
#define KPAD 72
#define VPAD 72
#define SQ 0
#define SKB(buf) (128 * QPAD + (buf) * BJ * KPAD)
#define SVB(buf) (128 * QPAD + 2 * BJ * KPAD + (buf) * BJ * VPAD)
#define SM_FLOATS (128 * QPAD + 2 * BJ * KPAD + 2 * BJ * VPAD)
#define SMEM_BYTES (SM_FLOATS * 4)      // 73,728 B -> 2 CTAs/SM

// fp32 -> tf32 bits (round-to-nearest on 10 mantissa bits, unbiased)
__device__ __forceinline__ uint32_t f2tf(float x) {
    uint32_t u;
    asm("cvt.rna.tf32.f32 %0, %1;" : "=r"(u) : "f"(x));
    return u;
}
__device__ __forceinline__ float f2tf_f(float x) { return __uint_as_float(f2tf(x)); }

// column pair-permutation: within each 8-group, (c, c+4) land at (2*(c&3), 2*(c&3)+1)
__device__ __forceinline__ int permc(int c) {
    return (c & ~7) | ((c & 3) << 1) | ((c >> 2) & 1);
}

// mma.sync m16n8k8 tf32: D = A*B + D (A row-major, B col-major)
__device__ __forceinline__ void mma8(float* c, const uint32_t* a, uint32_t b0, uint32_t b1) {
    asm volatile(
        "mma.sync.aligned.m16n8k8.row.col.f32.tf32.tf32.f32 "
        "{%0,%1,%2,%3}, {%4,%5,%6,%7}, {%8,%9}, {%0,%1,%2,%3};"
        : "+f"(c[0]), "+f"(c[1]), "+f"(c[2]), "+f"(c[3])
        : "r"(a[0]), "r"(a[1]), "r"(a[2]), "r"(a[3]), "r"(b0), "r"(b1));
}

__global__ __launch_bounds__(128, 2)
void attn_mma_kernel(const float* __restrict__ q, const float* __restrict__ k,
                     const float* __restrict__ v, const float* __restrict__ edge,
                     const int* __restrict__ mask, float* __restrict__ out)
{
    extern __shared__ float sm[];
    const int b  = blockIdx.y;
    const int q0 = blockIdx.x * BMQ;
    const int t  = threadIdx.x;
    const int w  = t >> 5;        // warp 0..3
    const int l  = t & 31;        // lane
    const int g  = l >> 2;        // groupID
    const int qd = l & 3;         // threadID_in_group

    // ---- Q tile: scale 1/8, tf32 round, permuted columns (b>=2 only) ----
    if (b >= 2) {
        const float4* q4 = reinterpret_cast<const float4*>(q + ((size_t)b * NN + q0) * DD);
        #pragma unroll
        for (int i = 0; i < 16; ++i) {
            int idx = t + i * 128;
            int r = idx >> 4, c4 = idx & 15;
            float4 x = q4[idx];
            float xs[4] = {x.x * 0.125f, x.y * 0.125f, x.z * 0.125f, x.w * 0.125f};
            #pragma unroll
            for (int e = 0; e < 4; ++e)
                sm[SQ + r * QPAD + permc(4 * c4 + e)] = f2tf_f(xs[e]);
        }
    }

    float sacc[2][4][4];           // S then P fragments
    float oacc[2][8][4];           // O fragments
    float lsum[2][2] = {{0.f, 0.f}, {0.f, 0.f}};
    #pragma unroll
    for (int mt = 0; mt < 2; ++mt)
        #pragma unroll
        for (int n = 0; n < 8; ++n)
            #pragma unroll
            for (int e = 0; e < 4; ++e) oacc[mt][n][e] = 0.f;

    const float4* kb = reinterpret_cast<const float4*>(k + (size_t)b * NN * DD);
    const float4* vb = reinterpret_cast<const float4*>(v + (size_t)b * NN * DD);

    float4 kr[4], vr[4];   // register-staged next tile (K: 16 floats, V: 16 floats)

    // prologue: fetch tile 0, stage into buffer 0
    {
        #pragma unroll
        for (int i = 0; i < 4; ++i) {
            if (b >= 2) kr[i] = kb[t + i * 128];
            vr[i] = vb[t + i * 128];
        }
        #pragma unroll
        for (int i = 0; i < 4; ++i) {
            int idx = t + i * 128;
            int r = idx >> 4, c4 = idx & 15;
            if (b >= 2) {
                float xs[4] = {kr[i].x, kr[i].y, kr[i].z, kr[i].w};
                #pragma unroll
                for (int e = 0; e < 4; ++e)
                    sm[SKB(0) + r * KPAD + permc(4 * c4 + e)] = f2tf_f(xs[e]);
            }
            float4 h;
            h.x = f2tf_f(vr[i].x); h.y = f2tf_f(vr[i].y);
            h.z = f2tf_f(vr[i].z); h.w = f2tf_f(vr[i].w);
            *reinterpret_cast<float4*>(&sm[SVB(0) + r * VPAD + 4 * c4]) = h;
        }
    }
    __syncthreads();

    int buf = 0;
    for (int kt = 0; kt < NTILES; ++kt) {
        const int j0 = kt * BJ;

        // ---- issue global fetch of NEXT tile (latency hidden by compute) ----
        if (kt + 1 < NTILES) {
            const size_t goff = (size_t)(j0 + BJ) * DD / 4;
            #pragma unroll
            for (int i = 0; i < 4; ++i) {
                if (b >= 2) kr[i] = kb[goff + t + i * 128];
                vr[i] = vb[goff + t + i * 128];
            }
        }

        // ---- QK^T: S = Q*K (single tf32 term, b>=2) ----
        if (b >= 2) {
            #pragma unroll
            for (int mt = 0; mt < 2; ++mt)
                #pragma unroll
                for (int nt = 0; nt < 4; ++nt)
                    #pragma unroll
                    for (int e = 0; e < 4; ++e) sacc[mt][nt][e] = 0.f;

            #pragma unroll
            for (int kk = 0; kk < 8; ++kk) {
                uint32_t aH[2][4];
                #pragma unroll
                for (int mt = 0; mt < 2; ++mt) {
                    int r0 = 32 * w + 16 * mt + g;
                    float2 x0 = *reinterpret_cast<const float2*>(&sm[SQ + r0 * QPAD + 8 * kk + 2 * qd]);
                    float2 x1 = *reinterpret_cast<const float2*>(&sm[SQ + (r0 + 8) * QPAD + 8 * kk + 2 * qd]);
                    aH[mt][0] = __float_as_uint(x0.x); aH[mt][1] = __float_as_uint(x1.x);
                    aH[mt][2] = __float_as_uint(x0.y); aH[mt][3] = __float_as_uint(x1.y);
                }
                #pragma unroll
                for (int nt = 0; nt < 4; ++nt) {
                    int jn = 8 * nt + g;
                    float2 bh = *reinterpret_cast<const float2*>(&sm[SKB(buf) + jn * KPAD + 8 * kk + 2 * qd]);
                    uint32_t bh0 = __float_as_uint(bh.x), bh1 = __float_as_uint(bh.y);
                    mma8(sacc[0][nt], aH[0], bh0, bh1);
                    mma8(sacc[1][nt], aH[1], bh0, bh1);
                }
            }
        }

        // ---- softmax numerators: P = exp(S) (masked) or exp(edge) ----
        // lsum accumulates the tf32-ROUNDED p (consistent with PV numerator).
        #pragma unroll
        for (int mt = 0; mt < 2; ++mt) {
            int row0 = q0 + 32 * w + 16 * mt + g;
            #pragma unroll
            for (int nt = 0; nt < 4; ++nt) {
                int col = j0 + 8 * nt + 2 * qd;
                float p0, p1, p2, p3;
                if (b < 2) {
                    float2 e0 = *reinterpret_cast<const float2*>(edge + (size_t)row0 * NN + col);
                    float2 e1 = *reinterpret_cast<const float2*>(edge + (size_t)(row0 + 8) * NN + col);
                    p0 = __expf(e0.x); p1 = __expf(e0.y);
                    p2 = __expf(e1.x); p3 = __expf(e1.y);
                } else {
                    int2 m0 = *reinterpret_cast<const int2*>(mask + ((size_t)b * NN + row0) * NN + col);
                    int2 m1 = *reinterpret_cast<const int2*>(mask + ((size_t)b * NN + row0 + 8) * NN + col);
                    p0 = m0.x ? 0.f : __expf(sacc[mt][nt][0]);
                    p1 = m0.y ? 0.f : __expf(sacc[mt][nt][1]);
                    p2 = m1.x ? 0.f : __expf(sacc[mt][nt][2]);
                    p3 = m1.y ? 0.f : __expf(sacc[mt][nt][3]);
                }
                float r0f = f2tf_f(p0), r1f = f2tf_f(p1);
                float r2f = f2tf_f(p2), r3f = f2tf_f(p3);
                lsum[mt][0] += r0f + r1f;
                lsum[mt][1] += r2f + r3f;
                sacc[mt][nt][0] = r0f;
                sacc[mt][nt][1] = r1f;
                sacc[mt][nt][2] = r2f;
                sacc[mt][nt][3] = r3f;
            }
        }

        // ---- PV: O += P*V (single term). A-frags via quad shuffles ----
        #pragma unroll
        for (int k2 = 0; k2 < 4; ++k2) {
            uint32_t pa[2][4];
            int src0 = (l & ~3) | (qd >> 1);
            int src1 = src0 + 2;
            #pragma unroll
            for (int mt = 0; mt < 2; ++mt) {
                float y00 = __shfl_sync(0xffffffffu, sacc[mt][k2][0], src0);
                float y01 = __shfl_sync(0xffffffffu, sacc[mt][k2][1], src0);
                float y10 = __shfl_sync(0xffffffffu, sacc[mt][k2][2], src0);
                float y11 = __shfl_sync(0xffffffffu, sacc[mt][k2][3], src0);
                float z00 = __shfl_sync(0xffffffffu, sacc[mt][k2][0], src1);
                float z01 = __shfl_sync(0xffffffffu, sacc[mt][k2][1], src1);
                float z10 = __shfl_sync(0xffffffffu, sacc[mt][k2][2], src1);
                float z11 = __shfl_sync(0xffffffffu, sacc[mt][k2][3], src1);
                bool od = (qd & 1);
                pa[mt][0] = __float_as_uint(od ? y01 : y00);
                pa[mt][1] = __float_as_uint(od ? y11 : y10);
                pa[mt][2] = __float_as_uint(od ? z01 : z00);
                pa[mt][3] = __float_as_uint(od ? z11 : z10);
            }
            #pragma unroll
            for (int nd = 0; nd < 8; ++nd) {
                int jrow = 8 * k2 + qd;
                uint32_t bh0 = __float_as_uint(sm[SVB(buf) + jrow * VPAD + 8 * nd + g]);
                uint32_t bh1 = __float_as_uint(sm[SVB(buf) + (jrow + 4) * VPAD + 8 * nd + g]);
                mma8(oacc[0][nd], pa[0], bh0, bh1);
                mma8(oacc[1][nd], pa[1], bh0, bh1);
            }
        }

        // ---- stage NEXT tile into the other buffer, then single sync ----
        if (kt + 1 < NTILES) {
            const int nb = buf ^ 1;
            #pragma unroll
            for (int i = 0; i < 4; ++i) {
                int idx = t + i * 128;
                int r = idx >> 4, c4 = idx & 15;
                if (b >= 2) {
                    float xs[4] = {kr[i].x, kr[i].y, kr[i].z, kr[i].w};
                    #pragma unroll
                    for (int e = 0; e < 4; ++e)
                        sm[SKB(nb) + r * KPAD + permc(4 * c4 + e)] = f2tf_f(xs[e]);
                }
                float4 h;
                h.x = f2tf_f(vr[i].x); h.y = f2tf_f(vr[i].y);
                h.z = f2tf_f(vr[i].z); h.w = f2tf_f(vr[i].w);
                *reinterpret_cast<float4*>(&sm[SVB(nb) + r * VPAD + 4 * c4]) = h;
            }
        }
        __syncthreads();
        buf ^= 1;
    }

    // ---- epilogue: reduce row sums across quad, scale, store ----
    float inv[2][2];
    #pragma unroll
    for (int mt = 0; mt < 2; ++mt)
        #pragma unroll
        for (int h = 0; h < 2; ++h) {
            float s = lsum[mt][h];
            s += __shfl_xor_sync(0xffffffffu, s, 1);
            s += __shfl_xor_sync(0xffffffffu, s, 2);
            inv[mt][h] = 1.0f / s;
        }
    #pragma unroll
    for (int mt = 0; mt < 2; ++mt) {
        int row0 = q0 + 32 * w + 16 * mt + g;
        #pragma unroll
        for (int nd = 0; nd < 8; ++nd) {
            int col = 8 * nd + 2 * qd;
            float2 r0v = make_float2(oacc[mt][nd][0] * inv[mt][0], oacc[mt][nd][1] * inv[mt][0]);
            float2 r1v = make_float2(oacc[mt][nd][2] * inv[mt][1], oacc[mt][nd][3] * inv[mt][1]);
            *reinterpret_cast<float2*>(out + ((size_t)b * NN + row0) * DD + col) = r0v;
            *reinterpret_cast<float2*>(out + ((size_t)b * NN + row0 + 8) * DD + col) = r1v;
        }
    }
}

extern "C" void kernel_launch(void* const* d_in, const int* in_sizes, int n_in,
                              void* d_out, int out_size)
{
    // Input identification (verified Rounds 1-3): q/k/v (2,097,152 elems each)
    // in insertion order q,k,v; edge = N*N; mask = B*N*N delivered as int32.
    const float* q = nullptr; const float* k = nullptr; const float* v = nullptr;
    const float* edge = nullptr; const int* mask = nullptr;

    const int QKV_ELEMS = BB * NN * DD;
    const int EDGE_ELEMS = NN * NN;
    int qkv_seen = 0;
    for (int i = 0; i < n_in; ++i) {
        if (in_sizes[i] == EDGE_ELEMS) edge = (const float*)d_in[i];
        else if (in_sizes[i] == QKV_ELEMS) {
            if (qkv_seen == 0) q = (const float*)d_in[i];
            else if (qkv_seen == 1) k = (const float*)d_in[i];
            else v = (const float*)d_in[i];
            ++qkv_seen;
        } else mask = (const int*)d_in[i];
    }

    cudaFuncSetAttribute(attn_mma_kernel, cudaFuncAttributeMaxDynamicSharedMemorySize, SMEM_BYTES);
    dim3 grid(NN / BMQ, BB);   // (16, 16) = 256 CTAs
    attn_mma_kernel<<<grid, 128, SMEM_BYTES>>>(q, k, v, edge, mask, (float*)d_out);
}

// round 12
// speedup vs baseline: 2.7276x; 1.3569x over previous
#include <cuda_runtime.h>
#include <cstdint>

// ---------------- problem shape ----------------
#define BB 16
#define NN 2048
#define DD 64
#define BMQ 128             // q rows per CTA (8 warps x 16 rows)
#define BJ 32               // KV rows per tile
#define NT 256              // threads per CTA
#define NTILES (NN / BJ)    // 64

// smem layout (float offsets). Q/K column-pair-permuted, V plain row-major.
// Pads = 72 -> conflict-free fragment loads per 16-lane phase.
#define QPAD 72
#define KPAD 72
#define VPAD 72
#define SQ 0
#define SKB(buf) (128 * QPAD + (buf) * BJ * KPAD)
#define SVB(buf) (128 * QPAD + 2 * BJ * KPAD + (buf) * BJ * VPAD)
#define SM_FLOATS (128 * QPAD + 2 * BJ * KPAD + 2 * BJ * VPAD)
#define SMEM_BYTES (SM_FLOATS * 4)      // 73,728 B -> 2 CTAs/SM

// fp32 -> tf32 bits (round-to-nearest, unbiased)
__device__ __forceinline__ uint32_t f2tf(float x) {
    uint32_t u;
    asm("cvt.rna.tf32.f32 %0, %1;" : "=r"(u) : "f"(x));
    return u;
}
__device__ __forceinline__ float f2tf_f(float x) { return __uint_as_float(f2tf(x)); }

// column pair-permutation: within each 8-group, (c, c+4) land at (2*(c&3), 2*(c&3)+1)
__device__ __forceinline__ int permc(int c) {
    return (c & ~7) | ((c & 3) << 1) | ((c >> 2) & 1);
}

// mma.sync m16n8k8 tf32: D = A*B + D (A row-major, B col-major)
__device__ __forceinline__ void mma8(float* c, const uint32_t* a, uint32_t b0, uint32_t b1) {
    asm volatile(
        "mma.sync.aligned.m16n8k8.row.col.f32.tf32.tf32.f32 "
        "{%0,%1,%2,%3}, {%4,%5,%6,%7}, {%8,%9}, {%0,%1,%2,%3};"
        : "+f"(c[0]), "+f"(c[1]), "+f"(c[2]), "+f"(c[3])
        : "r"(a[0]), "r"(a[1]), "r"(a[2]), "r"(a[3]), "r"(b0), "r"(b1));
}

__global__ __launch_bounds__(NT, 2)
void attn_mma_kernel(const float* __restrict__ q, const float* __restrict__ k,
                     const float* __restrict__ v, const float* __restrict__ edge,
                     const int* __restrict__ mask, float* __restrict__ out)
{
    extern __shared__ float sm[];
    const int b  = blockIdx.y;
    const int q0 = blockIdx.x * BMQ;
    const int t  = threadIdx.x;
    const int w  = t >> 5;        // warp 0..7, handles rows 16w..16w+15
    const int l  = t & 31;        // lane
    const int g  = l >> 2;        // groupID
    const int qd = l & 3;         // threadID_in_group

    // ---- Q tile: scale 1/8, tf32 round, permuted columns (b>=2 only) ----
    if (b >= 2) {
        const float4* q4 = reinterpret_cast<const float4*>(q + ((size_t)b * NN + q0) * DD);
        #pragma unroll
        for (int i = 0; i < 8; ++i) {
            int idx = t + i * NT;
            int r = idx >> 4, c4 = idx & 15;
            float4 x = q4[idx];
            float xs[4] = {x.x * 0.125f, x.y * 0.125f, x.z * 0.125f, x.w * 0.125f};
            #pragma unroll
            for (int e = 0; e < 4; ++e)
                sm[SQ + r * QPAD + permc(4 * c4 + e)] = f2tf_f(xs[e]);
        }
    }

    float sacc[4][4];              // S then P fragments (one m16 tile)
    float oacc[8][4];              // O fragments
    float lsum[2] = {0.f, 0.f};    // row sums for rows g / g+8
    #pragma unroll
    for (int n = 0; n < 8; ++n)
        #pragma unroll
        for (int e = 0; e < 4; ++e) oacc[n][e] = 0.f;

    const float4* kb = reinterpret_cast<const float4*>(k + (size_t)b * NN * DD);
    const float4* vb = reinterpret_cast<const float4*>(v + (size_t)b * NN * DD);

    float4 kr[2], vr[2];   // register-staged next tile

    // prologue: fetch tile 0, stage into buffer 0
    {
        #pragma unroll
        for (int i = 0; i < 2; ++i) {
            if (b >= 2) kr[i] = kb[t + i * NT];
            vr[i] = vb[t + i * NT];
        }
        #pragma unroll
        for (int i = 0; i < 2; ++i) {
            int idx = t + i * NT;
            int r = idx >> 4, c4 = idx & 15;
            if (b >= 2) {
                float xs[4] = {kr[i].x, kr[i].y, kr[i].z, kr[i].w};
                #pragma unroll
                for (int e = 0; e < 4; ++e)
                    sm[SKB(0) + r * KPAD + permc(4 * c4 + e)] = f2tf_f(xs[e]);
            }
            float4 h;
            h.x = f2tf_f(vr[i].x); h.y = f2tf_f(vr[i].y);
            h.z = f2tf_f(vr[i].z); h.w = f2tf_f(vr[i].w);
            *reinterpret_cast<float4*>(&sm[SVB(0) + r * VPAD + 4 * c4]) = h;
        }
    }
    __syncthreads();

    const int row0 = q0 + 16 * w + g;
    const int2*   mrow0 = reinterpret_cast<const int2*>(mask + ((size_t)b * NN + row0) * NN);
    const int2*   mrow1 = reinterpret_cast<const int2*>(mask + ((size_t)b * NN + row0 + 8) * NN);
    const float2* erow0 = reinterpret_cast<const float2*>(edge + (size_t)row0 * NN);
    const float2* erow1 = reinterpret_cast<const float2*>(edge + (size_t)(row0 + 8) * NN);

    int buf = 0;
    for (int kt = 0; kt < NTILES; ++kt) {
        const int j0 = kt * BJ;

        // ---- issue global fetch of NEXT K/V tile ----
        if (kt + 1 < NTILES) {
            const size_t goff = (size_t)(j0 + BJ) * DD / 4;
            #pragma unroll
            for (int i = 0; i < 2; ++i) {
                if (b >= 2) kr[i] = kb[goff + t + i * NT];
                vr[i] = vb[goff + t + i * NT];
            }
        }

        // ---- prefetch CURRENT tile's mask / edge (hidden behind QK MMAs) ----
        int2   m0[4], m1[4];
        float2 e0[4], e1[4];
        if (b < 2) {
            #pragma unroll
            for (int nt = 0; nt < 4; ++nt) {
                int c2 = (j0 + 8 * nt + 2 * qd) >> 1;
                e0[nt] = erow0[c2];
                e1[nt] = erow1[c2];
            }
        } else {
            #pragma unroll
            for (int nt = 0; nt < 4; ++nt) {
                int c2 = (j0 + 8 * nt + 2 * qd) >> 1;
                m0[nt] = __ldcs(&mrow0[c2]);
                m1[nt] = __ldcs(&mrow1[c2]);
            }
        }

        // ---- QK^T: S = Q*K (single tf32 term, b>=2) ----
        if (b >= 2) {
            #pragma unroll
            for (int nt = 0; nt < 4; ++nt)
                #pragma unroll
                for (int e = 0; e < 4; ++e) sacc[nt][e] = 0.f;

            #pragma unroll
            for (int kk = 0; kk < 8; ++kk) {
                uint32_t a[4];
                int r0 = 16 * w + g;
                float2 x0 = *reinterpret_cast<const float2*>(&sm[SQ + r0 * QPAD + 8 * kk + 2 * qd]);
                float2 x1 = *reinterpret_cast<const float2*>(&sm[SQ + (r0 + 8) * QPAD + 8 * kk + 2 * qd]);
                a[0] = __float_as_uint(x0.x); a[1] = __float_as_uint(x1.x);
                a[2] = __float_as_uint(x0.y); a[3] = __float_as_uint(x1.y);
                #pragma unroll
                for (int nt = 0; nt < 4; ++nt) {
                    int jn = 8 * nt + g;
                    float2 bh = *reinterpret_cast<const float2*>(&sm[SKB(buf) + jn * KPAD + 8 * kk + 2 * qd]);
                    mma8(sacc[nt], a, __float_as_uint(bh.x), __float_as_uint(bh.y));
                }
            }
        }

        // ---- softmax numerators: P = exp(S) (masked) or exp(edge) ----
        #pragma unroll
        for (int nt = 0; nt < 4; ++nt) {
            float p0, p1, p2, p3;
            if (b < 2) {
                p0 = __expf(e0[nt].x); p1 = __expf(e0[nt].y);
                p2 = __expf(e1[nt].x); p3 = __expf(e1[nt].y);
            } else {
                p0 = m0[nt].x ? 0.f : __expf(sacc[nt][0]);
                p1 = m0[nt].y ? 0.f : __expf(sacc[nt][1]);
                p2 = m1[nt].x ? 0.f : __expf(sacc[nt][2]);
                p3 = m1[nt].y ? 0.f : __expf(sacc[nt][3]);
            }
            float r0f = f2tf_f(p0), r1f = f2tf_f(p1);
            float r2f = f2tf_f(p2), r3f = f2tf_f(p3);
            lsum[0] += r0f + r1f;
            lsum[1] += r2f + r3f;
            sacc[nt][0] = r0f; sacc[nt][1] = r1f;
            sacc[nt][2] = r2f; sacc[nt][3] = r3f;
        }

        // ---- PV: O += P*V. A-frags via quad shuffles ----
        #pragma unroll
        for (int k2 = 0; k2 < 4; ++k2) {
            uint32_t pa[4];
            int src0 = (l & ~3) | (qd >> 1);
            int src1 = src0 + 2;
            float y00 = __shfl_sync(0xffffffffu, sacc[k2][0], src0);
            float y01 = __shfl_sync(0xffffffffu, sacc[k2][1], src0);
            float y10 = __shfl_sync(0xffffffffu, sacc[k2][2], src0);
            float y11 = __shfl_sync(0xffffffffu, sacc[k2][3], src0);
            float z00 = __shfl_sync(0xffffffffu, sacc[k2][0], src1);
            float z01 = __shfl_sync(0xffffffffu, sacc[k2][1], src1);
            float z10 = __shfl_sync(0xffffffffu, sacc[k2][2], src1);
            float z11 = __shfl_sync(0xffffffffu, sacc[k2][3], src1);
            bool od = (qd & 1);
            pa[0] = __float_as_uint(od ? y01 : y00);
            pa[1] = __float_as_uint(od ? y11 : y10);
            pa[2] = __float_as_uint(od ? z01 : z00);
            pa[3] = __float_as_uint(od ? z11 : z10);
            #pragma unroll
            for (int nd = 0; nd < 8; ++nd) {
                int jrow = 8 * k2 + qd;
                uint32_t bh0 = __float_as_uint(sm[SVB(buf) + jrow * VPAD + 8 * nd + g]);
                uint32_t bh1 = __float_as_uint(sm[SVB(buf) + (jrow + 4) * VPAD + 8 * nd + g]);
                mma8(oacc[nd], pa, bh0, bh1);
            }
        }

        // ---- stage NEXT tile into the other buffer, then single sync ----
        if (kt + 1 < NTILES) {
            const int nb = buf ^ 1;
            #pragma unroll
            for (int i = 0; i < 2; ++i) {
                int idx = t + i * NT;
                int r = idx >> 4, c4 = idx & 15;
                if (b >= 2) {
                    float xs[4] = {kr[i].x, kr[i].y, kr[i].z, kr[i].w};
                    #pragma unroll
                    for (int e = 0; e < 4; ++e)
                        sm[SKB(nb) + r * KPAD + permc(4 * c4 + e)] = f2tf_f(xs[e]);
                }
                float4 h;
                h.x = f2tf_f(vr[i].x); h.y = f2tf_f(vr[i].y);
                h.z = f2tf_f(vr[i].z); h.w = f2tf_f(vr[i].w);
                *reinterpret_cast<float4*>(&sm[SVB(nb) + r * VPAD + 4 * c4]) = h;
            }
        }
        __syncthreads();
        buf ^= 1;
    }

    // ---- epilogue: reduce row sums across quad, scale, store ----
    float s0 = lsum[0];
    s0 += __shfl_xor_sync(0xffffffffu, s0, 1);
    s0 += __shfl_xor_sync(0xffffffffu, s0, 2);
    float s1 = lsum[1];
    s1 += __shfl_xor_sync(0xffffffffu, s1, 1);
    s1 += __shfl_xor_sync(0xffffffffu, s1, 2);
    float inv0 = 1.0f / s0, inv1 = 1.0f / s1;
    #pragma unroll
    for (int nd = 0; nd < 8; ++nd) {
        int col = 8 * nd + 2 * qd;
        float2 r0v = make_float2(oacc[nd][0] * inv0, oacc[nd][1] * inv0);
        float2 r1v = make_float2(oacc[nd][2] * inv1, oacc[nd][3] * inv1);
        *reinterpret_cast<float2*>(out + ((size_t)b * NN + row0) * DD + col) = r0v;
        *reinterpret_cast<float2*>(out + ((size_t)b * NN + row0 + 8) * DD + col) = r1v;
    }
}

extern "C" void kernel_launch(void* const* d_in, const int* in_sizes, int n_in,
                              void* d_out, int out_size)
{
    // Input identification (verified Rounds 1-3): q/k/v (2,097,152 elems each)
    // in insertion order q,k,v; edge = N*N; mask = B*N*N delivered as int32.
    const float* q = nullptr; const float* k = nullptr; const float* v = nullptr;
    const float* edge = nullptr; const int* mask = nullptr;

    const int QKV_ELEMS = BB * NN * DD;
    const int EDGE_ELEMS = NN * NN;
    int qkv_seen = 0;
    for (int i = 0; i < n_in; ++i) {
        if (in_sizes[i] == EDGE_ELEMS) edge = (const float*)d_in[i];
        else if (in_sizes[i] == QKV_ELEMS) {
            if (qkv_seen == 0) q = (const float*)d_in[i];
            else if (qkv_seen == 1) k = (const float*)d_in[i];
            else v = (const float*)d_in[i];
            ++qkv_seen;
        } else mask = (const int*)d_in[i];
    }

    cudaFuncSetAttribute(attn_mma_kernel, cudaFuncAttributeMaxDynamicSharedMemorySize, SMEM_BYTES);
    dim3 grid(NN / BMQ, BB);   // (16, 16) = 256 CTAs
    attn_mma_kernel<<<grid, NT, SMEM_BYTES>>>(q, k, v, edge, mask, (float*)d_out);
}